// round 17
// baseline (speedup 1.0000x reference)
#include <cuda_runtime.h>
#include <cuda_fp16.h>
#include <cstdint>

// Problem constants (fixed-shape problem: H=8, MH=8, N_NODES=500000)
#define H_DIM 8
#define MH_DIM 8
#define FEAT 64              // H*MH per sign
#define REC 128              // 2 signs * FEAT values per node record
#define MAX_NODES 500000
#define TILE_N 64            // nodes per transpose tile (R13-proven)

// Node-major scratch in fp16: [node][sign][h][mh], 256B per node,
// deg-normalization folded in. uint4 type guarantees 16B alignment.
__device__ uint4 g_pk_raw[(size_t)MAX_NODES * REC / 8];

// ---- L2 eviction-priority helpers (cache_hint form) ----
__device__ __forceinline__ uint64_t mk_evict_last_policy() {
    uint64_t pol;
    asm("createpolicy.fractional.L2::evict_last.b64 %0, 1.0;" : "=l"(pol));
    return pol;
}
__device__ __forceinline__ void st_hint_v4(void* p, uint4 v, uint64_t pol) {
    asm volatile("st.global.L2::cache_hint.v4.b32 [%0], {%1,%2,%3,%4}, %5;"
                 :: "l"(p), "r"(v.x), "r"(v.y), "r"(v.z), "r"(v.w), "l"(pol));
}
__device__ __forceinline__ uint4 ld_hint_v4(const void* p, uint64_t pol) {
    uint4 r;
    asm volatile("ld.global.L2::cache_hint.v4.u32 {%0,%1,%2,%3}, [%4], %5;"
                 : "=r"(r.x), "=r"(r.y), "=r"(r.z), "=r"(r.w)
                 : "l"(p), "l"(pol));
    return r;
}

// fp16 tile: 64 feat-rows x 32 half2-units (unit u = nodes 2u, 2u+1).
// Row = 128B. Swizzle X(f) = (f&30) ^ 4*(f>>5) applied to the unit index:
//  - even X preserves the (2g, 2g+1) pair -> phase-1 STS.64 stays aligned
//  - phase-1: 16 distinct even units/half-warp -> all 32 banks, conflict-free
//  - phase-2: bank bits {p0, p1^j1, j2^(c>>2), c&3} -> 32 distinct, conflict-free
__device__ __forceinline__ int hu(int f, int u) {
    int x = (f & 30) ^ ((f >> 5) << 2);
    return f * 32 + (u ^ x);
}

// ---------------------------------------------------------------------------
// Kernel 1: transpose [h][mh][N] -> scratch[k][sign][h][mh] fp16, folding
// 1/max(deg,1) AT LOAD TIME (phase 1). Block: 256 threads, 64 nodes x 64 feats.
// gridDim.y = sign (x dispatched first -> TLB working set stays one-sign).
// Phase 2 is pure repack: 8 LDS + 8 PRMT + 2 STG per 32B (two nodes).
// ---------------------------------------------------------------------------
__global__ __launch_bounds__(256) void transpose_fold_sign_kernel(
    const float* __restrict__ phi_pos,
    const float* __restrict__ phi_neg,
    const float* __restrict__ deg_pos,
    const float* __restrict__ deg_neg,
    int n_nodes)
{
    __shared__ __align__(16) unsigned tile[64 * 32];   // 8KB half2 tile
    __shared__ __align__(16) float inv_t[H_DIM][68];   // transposed, padded

    const int sgn = blockIdx.y;                 // 0 = pos, 1 = neg
    const float* __restrict__ phi = sgn ? phi_neg : phi_pos;
    const float* __restrict__ deg = sgn ? deg_neg : deg_pos;
    const int sgn8 = sgn * 8;                   // chunk offset in record

    const int k0 = blockIdx.x * TILE_N;
    const int t  = threadIdx.x;
    const uint64_t pol = mk_evict_last_policy();
    const bool full = (k0 + TILE_N <= n_nodes) && ((n_nodes & 3) == 0);

    // ---- inv_t[h][node]: 64 nodes * 8 heads, coalesced deg read ----
    #pragma unroll
    for (int it = 0; it < 2; ++it) {
        int idx  = t + it * 256;            // node*8 + h
        int node = idx >> 3;
        int h    = idx & 7;
        int k    = k0 + node;
        float d  = 1.0f;
        if (k < n_nodes)
            d = __ldcs(deg + (size_t)k * H_DIM + h);
        inv_t[h][node] = 1.0f / fmaxf(d, 1.0f);
    }
    __syncthreads();   // phase 1 consumes inv_t

    // ---- phase 1: 64 feat-rows x 16 float4 groups; scale+convert here ----
    if (full) {
        #pragma unroll
        for (int it = 0; it < 4; ++it) {
            int l = t + it * 256;           // 0..1023
            int f = l >> 4;                 // feat row 0..63
            int g = l & 15;                 // float4 group (4 nodes)
            int h = f >> 3;
            float4 v  = __ldcs(reinterpret_cast<const float4*>(
                phi + (size_t)f * n_nodes + k0 + 4 * g));
            float4 iv = *reinterpret_cast<const float4*>(&inv_t[h][4 * g]);
            __half2 ha = __floats2half2_rn(v.x * iv.x, v.y * iv.y);
            __half2 hb = __floats2half2_rn(v.z * iv.z, v.w * iv.w);
            uint2 u2;
            __builtin_memcpy(&u2.x, &ha, 4);
            __builtin_memcpy(&u2.y, &hb, 4);
            *reinterpret_cast<uint2*>(&tile[hu(f, 2 * g)]) = u2;
        }
    } else {
        #pragma unroll 4
        for (int it = 0; it < 16; ++it) {
            int l  = t + it * 256;          // 64*64 = 4096 elements
            int f  = l >> 6;
            int kk = l & 63;
            int k  = k0 + kk;
            int h  = f >> 3;
            float v = 0.0f;
            if (k < n_nodes)
                v = __ldcs(phi + (size_t)f * n_nodes + k) * inv_t[h][kk];
            __half hv = __float2half_rn(v);
            char* base = reinterpret_cast<char*>(&tile[hu(f, kk >> 1)]);
            *reinterpret_cast<__half*>(base + (kk & 1) * 2) = hv;
        }
    }
    __syncthreads();

    // ---- phase 2: 32 node-pairs x 8 chunks = 256 tasks (1/thread) ----
    {
        int p  = t >> 3;                    // half2 unit = nodes 2p, 2p+1
        int c  = t & 7;                     // head chunk (feats 8c..8c+7)
        int ka = k0 + 2 * p;
        int kb = ka + 1;

        unsigned v[8];
        #pragma unroll
        for (int j = 0; j < 8; ++j)
            v[j] = tile[hu(8 * c + j, p)];

        uint4 ua, ub;   // node 2p (lo halves), node 2p+1 (hi halves)
        ua.x = __byte_perm(v[0], v[1], 0x5410);
        ua.y = __byte_perm(v[2], v[3], 0x5410);
        ua.z = __byte_perm(v[4], v[5], 0x5410);
        ua.w = __byte_perm(v[6], v[7], 0x5410);
        ub.x = __byte_perm(v[0], v[1], 0x7632);
        ub.y = __byte_perm(v[2], v[3], 0x7632);
        ub.z = __byte_perm(v[4], v[5], 0x7632);
        ub.w = __byte_perm(v[6], v[7], 0x7632);

        if (ka < n_nodes)
            st_hint_v4(g_pk_raw + (size_t)ka * (REC / 8) + sgn8 + c, ua, pol);
        if (kb < n_nodes)
            st_hint_v4(g_pk_raw + (size_t)kb * (REC / 8) + sgn8 + c, ub, pol);
    }
}

// ---------------------------------------------------------------------------
// Kernel 2: gather + dot (champion, byte-identical). 8 threads per query;
// thread j = head j. out layout: [pos: nq*8][neg: nq*8]
// ---------------------------------------------------------------------------
__global__ __launch_bounds__(256) void gather_dot_kernel(
    const float* __restrict__ q_phi,
    const int*   __restrict__ k_indices,
    float* __restrict__ out,
    int nq)
{
    int t = blockIdx.x * blockDim.x + threadIdx.x;
    int i = t >> 3;
    if (i >= nq) return;
    int h = t & 7;

    const uint64_t pol = mk_evict_last_policy();

    int k = __ldcs(k_indices + i);

    const float4* qp = reinterpret_cast<const float4*>(
        q_phi + (size_t)i * FEAT + h * MH_DIM);
    float4 q0 = __ldcs(qp);
    float4 q1 = __ldcs(qp + 1);

    const uint4* rec = g_pk_raw + (size_t)k * (REC / 8);
    uint4 pr = ld_hint_v4(rec + h, pol);
    uint4 nr = ld_hint_v4(rec + 8 + h, pol);

    const __half2* ph = reinterpret_cast<const __half2*>(&pr);
    const __half2* nh = reinterpret_cast<const __half2*>(&nr);

    float2 p0 = __half22float2(ph[0]);
    float2 p1 = __half22float2(ph[1]);
    float2 p2 = __half22float2(ph[2]);
    float2 p3 = __half22float2(ph[3]);
    float2 n0 = __half22float2(nh[0]);
    float2 n1 = __half22float2(nh[1]);
    float2 n2 = __half22float2(nh[2]);
    float2 n3 = __half22float2(nh[3]);

    float dp = q0.x * p0.x + q0.y * p0.y + q0.z * p1.x + q0.w * p1.y
             + q1.x * p2.x + q1.y * p2.y + q1.z * p3.x + q1.w * p3.y;
    float dn = q0.x * n0.x + q0.y * n0.y + q0.z * n1.x + q0.w * n1.y
             + q1.x * n2.x + q1.y * n2.y + q1.z * n3.x + q1.w * n3.y;

    __stcs(out + (size_t)i * H_DIM + h, dp);
    __stcs(out + (size_t)nq * H_DIM + (size_t)i * H_DIM + h, dn);
}

extern "C" void kernel_launch(void* const* d_in, const int* in_sizes, int n_in,
                              void* d_out, int out_size)
{
    const float* q_phi   = (const float*)d_in[0];
    const float* phi_pos = (const float*)d_in[1];
    const float* phi_neg = (const float*)d_in[2];
    const float* deg_pos = (const float*)d_in[3];
    const float* deg_neg = (const float*)d_in[4];
    const int*   k_idx   = (const int*)d_in[5];

    int nq      = in_sizes[5];                    // k_indices has N_Q elements
    int n_nodes = in_sizes[3] / H_DIM;            // deg_pos is [N][H]
    if (n_nodes > MAX_NODES) n_nodes = MAX_NODES;

    int tblocks = (n_nodes + TILE_N - 1) / TILE_N;
    dim3 tgrid(tblocks, 2);                       // y = sign; x dispatched first
    transpose_fold_sign_kernel<<<tgrid, 256>>>(phi_pos, phi_neg,
                                               deg_pos, deg_neg, n_nodes);

    int total   = nq * H_DIM;
    int gblocks = (total + 255) / 256;
    gather_dot_kernel<<<gblocks, 256>>>(q_phi, k_idx, (float*)d_out, nq);
}